// round 8
// baseline (speedup 1.0000x reference)
#include <cuda_runtime.h>
#include <math.h>

#define B_TOTAL 32768
#define X_DIM   30
#define Y_DIM   30
#define F_DIM   6
#define CELLS   (X_DIM * Y_DIM)      // 900
#define THREADS 256
#define PROD_BLOCKS 113               // 113 * 8 cells = 904 >= 900
#define CONS_BLOCKS 32                // 32 * 256 * 4 = 32768 batch elems
#define ITERS 4
#define GRID (PROD_BLOCKS + CONS_BLOCKS)  // 145 <= 148 SMs: one CTA per SM

__device__ float    g_S[CELLS];
__device__ unsigned g_ctr  = 0;   // producer-done counter (release/acquire)
__device__ unsigned g_done = 0;   // consumer completion counter (for reset)

__global__ void __launch_bounds__(THREADS)
fused_kernel(const float* __restrict__ phi,
             const float* __restrict__ succ,
             const float* __restrict__ w,
             float* __restrict__ out) {
    const int tid = threadIdx.x;
    const int bid = blockIdx.x;

    const float w0 = __ldg(&w[0]), w1 = __ldg(&w[1]), w2 = __ldg(&w[2]);
    const float w3 = __ldg(&w[3]), w4 = __ldg(&w[4]), w5 = __ldg(&w[5]);

    if (bid < PROD_BLOCKS) {
        // ================= PRODUCER: 8 cells per block =================
        const int h    = tid >> 7;
        const int p    = tid & 127;
        const int lane = tid & 31;
        const int w4g  = (tid >> 5) & 3;
        const int cell0 = bid * 8 + h * 4;
        const bool valid = cell0 < CELLS;

        __shared__ float smax[2][4][4];
        __shared__ float ssum[2][4][4][2];

        float v[4], x[4];
        if (valid) {
            // byte offset = p*21600 + cell0*24 (cell0 % 4 == 0) -> 16B aligned
            const float4* base =
                (const float4*)(succ + (size_t)p * (CELLS * F_DIM) + (size_t)cell0 * F_DIM);
            const float4 q0 = base[0], q1 = base[1], q2 = base[2];
            const float4 q3 = base[3], q4 = base[4], q5 = base[5];

            v[0] = q0.x*w0 + q0.y*w1 + q0.z*w2 + q0.w*w3 + q1.x*w4 + q1.y*w5;
            v[1] = q1.z*w0 + q1.w*w1 + q2.x*w2 + q2.y*w3 + q2.z*w4 + q2.w*w5;
            v[2] = q3.x*w0 + q3.y*w1 + q3.z*w2 + q3.w*w3 + q4.x*w4 + q4.y*w5;
            v[3] = q4.z*w0 + q4.w*w1 + q5.x*w2 + q5.y*w3 + q5.z*w4 + q5.w*w5;

#pragma unroll
            for (int j = 0; j < 4; ++j) x[j] = v[j] / 0.001f;   // match vs / T

#pragma unroll
            for (int j = 0; j < 4; ++j) {
                float mm = x[j];
#pragma unroll
                for (int s = 16; s > 0; s >>= 1)
                    mm = fmaxf(mm, __shfl_xor_sync(0xFFFFFFFFu, mm, s));
                if (lane == 0) smax[h][j][w4g] = mm;
            }
        }
        __syncthreads();

        if (valid) {
#pragma unroll
            for (int j = 0; j < 4; ++j) {
                const float mx = fmaxf(fmaxf(smax[h][j][0], smax[h][j][1]),
                                       fmaxf(smax[h][j][2], smax[h][j][3]));
                float e  = __expf(x[j] - mx);
                float ev = e * v[j];
#pragma unroll
                for (int s = 16; s > 0; s >>= 1) {
                    e  += __shfl_xor_sync(0xFFFFFFFFu, e,  s);
                    ev += __shfl_xor_sync(0xFFFFFFFFu, ev, s);
                }
                if (lane == 0) { ssum[h][j][w4g][0] = e; ssum[h][j][w4g][1] = ev; }
            }
        }
        __syncthreads();

        if (valid && (tid & 127) < 4) {
            const int j = tid & 3;
            const float se  = ssum[h][j][0][0] + ssum[h][j][1][0]
                            + ssum[h][j][2][0] + ssum[h][j][3][0];
            const float sev = ssum[h][j][0][1] + ssum[h][j][1][1]
                            + ssum[h][j][2][1] + ssum[h][j][3][1];
            g_S[cell0 + j] = sev / se;
        }
        __syncthreads();   // CTA fence: g_S writes happen-before the release
        if (tid == 0) {
            unsigned* ctr = &g_ctr;
            asm volatile("red.release.gpu.global.add.u32 [%0], 1;"
                         :: "l"(ctr) : "memory");
        }
    } else {
        // ====== CONSUMER: 4 batch elems per thread, 1024 per block ======
        const int e0 = (bid - PROD_BLOCKS) * (THREADS * ITERS) + tid;

        float pr0[ITERS], pr1[ITERS];
        int   is0[ITERS], ie0[ITERS], is1[ITERS], ie1[ITERS];

        // All 20 float4 DRAM loads issue here, before the spin -> latency
        // fully overlaps producer execution.
#pragma unroll
        for (int k = 0; k < ITERS; ++k) {
            const int e = e0 + k * THREADS;
            const float4* ph = (const float4*)(phi + (size_t)e * 20);
            const float4 a0 = ph[0];
            const float4 a1 = ph[1];
            const float4 a2 = ph[2];
            const float4 a3 = ph[3];
            const float4 a4 = ph[4];

            pr0[k] = a0.x*w0 + a0.y*w1 + a0.z*w2 + a0.w*w3 + a1.x*w4 + a1.y*w5;
            pr1[k] = a2.z*w0 + a2.w*w1 + a3.x*w2 + a3.y*w3 + a3.z*w4 + a3.w*w5;

            is0[k] = (int)a1.z * Y_DIM + (int)a1.w;
            ie0[k] = (int)a2.x * Y_DIM + (int)a2.y;
            is1[k] = (int)a4.x * Y_DIM + (int)a4.y;
            ie1[k] = (int)a4.z * Y_DIM + (int)a4.w;
        }

        // Tight acquire-spin; only 32 spinner warps, each on its own SM.
        if (tid == 0) {
            const unsigned* ctr = &g_ctr;
            unsigned vct;
            do {
                asm volatile("ld.acquire.gpu.global.u32 %0, [%1];"
                             : "=r"(vct) : "l"(ctr) : "memory");
            } while (vct < PROD_BLOCKS);
        }
        __syncthreads();

#pragma unroll
        for (int k = 0; k < ITERS; ++k) {
            const int e = e0 + k * THREADS;
            const float d0 = pr0[k] + (__ldcg(&g_S[ie0[k]]) - __ldcg(&g_S[is0[k]]));
            const float d1 = pr1[k] + (__ldcg(&g_S[ie1[k]]) - __ldcg(&g_S[is1[k]]));
            const float diff = d0 - d1;
            float2 r;
            r.x = 1.0f / (1.0f + __expf(-diff));
            r.y = 1.0f / (1.0f + __expf( diff));
            ((float2*)out)[e] = r;
        }

        // Reset counters for next graph replay: last consumer block does it.
        __syncthreads();
        if (tid == 0) {
            const unsigned d = atomicAdd(&g_done, 1u);
            if (d == CONS_BLOCKS - 1) {
                atomicExch(&g_ctr,  0u);
                atomicExch(&g_done, 0u);
            }
        }
    }
}

extern "C" void kernel_launch(void* const* d_in, const int* in_sizes, int n_in,
                              void* d_out, int out_size) {
    const float* phi  = (const float*)d_in[0];   // (32768, 2, 10)
    const float* succ = (const float*)d_in[1];   // (128, 30, 30, 6)
    const float* w    = (const float*)d_in[2];   // (6,)
    float* out = (float*)d_out;                  // (32768, 2, 1)

    fused_kernel<<<GRID, THREADS>>>(phi, succ, w, out);
}

// round 9
// speedup vs baseline: 1.1800x; 1.1800x over previous
#include <cuda_runtime.h>
#include <math.h>

#define B_TOTAL 32768
#define X_DIM   30
#define Y_DIM   30
#define F_DIM   6
#define CELLS   (X_DIM * Y_DIM)      // 900
#define THREADS 256
#define PROD_BLOCKS 113               // 113 * 8 cells = 904 >= 900
#define PACK_BLOCKS 35                // wave-1 filler: 35*256*4 = 35840 >= 32768
#define WAVE1 (PROD_BLOCKS + PACK_BLOCKS)   // 148 = one CTA per SM
#define FIN_BLOCKS (B_TOTAL / THREADS)      // 128 finishers (wave 2)
#define GRID (WAVE1 + FIN_BLOCKS)           // 276
#define SMEM_FORCE (120 * 1024)             // force 1 CTA/SM

__device__ float    g_S[CELLS];
__device__ uint4    g_pack[B_TOTAL];
__device__ unsigned g_ctr  = 0;   // wave-1 completion counter (release/acquire)
__device__ unsigned g_done = 0;   // finisher completion counter (for reset)

__global__ void __launch_bounds__(THREADS)
fused_kernel(const float* __restrict__ phi,
             const float* __restrict__ succ,
             const float* __restrict__ w,
             float* __restrict__ out) {
    extern __shared__ char dummy_smem[];   // occupancy forcing only
    const int tid = threadIdx.x;
    const int bid = blockIdx.x;

    const float w0 = __ldg(&w[0]), w1 = __ldg(&w[1]), w2 = __ldg(&w[2]);
    const float w3 = __ldg(&w[3]), w4 = __ldg(&w[4]), w5 = __ldg(&w[5]);

    if (bid < PROD_BLOCKS) {
        // ================= WAVE 1a — PRODUCER: 8 cells per block =================
        const int h    = tid >> 7;
        const int p    = tid & 127;
        const int lane = tid & 31;
        const int w4g  = (tid >> 5) & 3;
        const int cell0 = bid * 8 + h * 4;
        const bool valid = cell0 < CELLS;

        __shared__ float smax[2][4][4];
        __shared__ float ssum[2][4][4][2];

        float v[4], x[4];
        if (valid) {
            // byte offset = p*21600 + cell0*24 (cell0 % 4 == 0) -> 16B aligned
            const float4* base =
                (const float4*)(succ + (size_t)p * (CELLS * F_DIM) + (size_t)cell0 * F_DIM);
            const float4 q0 = base[0], q1 = base[1], q2 = base[2];
            const float4 q3 = base[3], q4 = base[4], q5 = base[5];

            v[0] = q0.x*w0 + q0.y*w1 + q0.z*w2 + q0.w*w3 + q1.x*w4 + q1.y*w5;
            v[1] = q1.z*w0 + q1.w*w1 + q2.x*w2 + q2.y*w3 + q2.z*w4 + q2.w*w5;
            v[2] = q3.x*w0 + q3.y*w1 + q3.z*w2 + q3.w*w3 + q4.x*w4 + q4.y*w5;
            v[3] = q4.z*w0 + q4.w*w1 + q5.x*w2 + q5.y*w3 + q5.z*w4 + q5.w*w5;

#pragma unroll
            for (int j = 0; j < 4; ++j) x[j] = v[j] / 0.001f;   // match vs / T

#pragma unroll
            for (int j = 0; j < 4; ++j) {
                float mm = x[j];
#pragma unroll
                for (int s = 16; s > 0; s >>= 1)
                    mm = fmaxf(mm, __shfl_xor_sync(0xFFFFFFFFu, mm, s));
                if (lane == 0) smax[h][j][w4g] = mm;
            }
        }
        __syncthreads();

        if (valid) {
#pragma unroll
            for (int j = 0; j < 4; ++j) {
                const float mx = fmaxf(fmaxf(smax[h][j][0], smax[h][j][1]),
                                       fmaxf(smax[h][j][2], smax[h][j][3]));
                float e  = __expf(x[j] - mx);
                float ev = e * v[j];
#pragma unroll
                for (int s = 16; s > 0; s >>= 1) {
                    e  += __shfl_xor_sync(0xFFFFFFFFu, e,  s);
                    ev += __shfl_xor_sync(0xFFFFFFFFu, ev, s);
                }
                if (lane == 0) { ssum[h][j][w4g][0] = e; ssum[h][j][w4g][1] = ev; }
            }
        }
        __syncthreads();

        if (valid && (tid & 127) < 4) {
            const int j = tid & 3;
            const float se  = ssum[h][j][0][0] + ssum[h][j][1][0]
                            + ssum[h][j][2][0] + ssum[h][j][3][0];
            const float sev = ssum[h][j][0][1] + ssum[h][j][1][1]
                            + ssum[h][j][2][1] + ssum[h][j][3][1];
            g_S[cell0 + j] = sev / se;
        }
        __syncthreads();   // g_S writes happen-before the release
        if (tid == 0) {
            unsigned* ctr = &g_ctr;
            asm volatile("red.release.gpu.global.add.u32 [%0], 1;"
                         :: "l"(ctr) : "memory");
        }
    } else if (bid < WAVE1) {
        // ================= WAVE 1b — PACKER: 4 elems per thread =================
        const int base = (bid - PROD_BLOCKS) * (THREADS * 4) + tid;
#pragma unroll
        for (int k = 0; k < 4; ++k) {
            const int e = base + k * THREADS;
            if (e < B_TOTAL) {
                const float4* ph = (const float4*)(phi + (size_t)e * 20);
                const float4 a0 = ph[0];
                const float4 a1 = ph[1];
                const float4 a2 = ph[2];
                const float4 a3 = ph[3];
                const float4 a4 = ph[4];

                const float pr0 = a0.x*w0 + a0.y*w1 + a0.z*w2 + a0.w*w3 + a1.x*w4 + a1.y*w5;
                const float pr1 = a2.z*w0 + a2.w*w1 + a3.x*w2 + a3.y*w3 + a3.z*w4 + a3.w*w5;

                const unsigned is0 = (unsigned)((int)a1.z * Y_DIM + (int)a1.w);
                const unsigned ie0 = (unsigned)((int)a2.x * Y_DIM + (int)a2.y);
                const unsigned is1 = (unsigned)((int)a4.x * Y_DIM + (int)a4.y);
                const unsigned ie1 = (unsigned)((int)a4.z * Y_DIM + (int)a4.w);

                uint4 pk;
                pk.x = __float_as_uint(pr0);
                pk.y = __float_as_uint(pr1);
                pk.z = is0 | (ie0 << 16);
                pk.w = is1 | (ie1 << 16);
                g_pack[e] = pk;
            }
        }
        __syncthreads();   // pack stores issued before release
        if (tid == 0) {
            unsigned* ctr = &g_ctr;
            asm volatile("red.release.gpu.global.add.u32 [%0], 1;"
                         :: "l"(ctr) : "memory");
        }
    } else {
        // ================= WAVE 2 — FINISHER =================
        // Only gets an SM slot after a wave-1 CTA exits; spin is a short guard.
        const int b = (bid - WAVE1) * THREADS + tid;

        if (tid == 0) {
            const unsigned* ctr = &g_ctr;
            unsigned vct;
            do {
                asm volatile("ld.acquire.gpu.global.u32 %0, [%1];"
                             : "=r"(vct) : "l"(ctr) : "memory");
            } while (vct < WAVE1);
        }
        __syncthreads();

        const uint4 pk = g_pack[b];
        const float pr0 = __uint_as_float(pk.x);
        const float pr1 = __uint_as_float(pk.y);
        const int is0 = pk.z & 0xFFFF;
        const int ie0 = pk.z >> 16;
        const int is1 = pk.w & 0xFFFF;
        const int ie1 = pk.w >> 16;

        const float d0 = pr0 + (__ldcg(&g_S[ie0]) - __ldcg(&g_S[is0]));
        const float d1 = pr1 + (__ldcg(&g_S[ie1]) - __ldcg(&g_S[is1]));

        const float diff = d0 - d1;
        float2 r;
        r.x = 1.0f / (1.0f + __expf(-diff));
        r.y = 1.0f / (1.0f + __expf( diff));
        ((float2*)out)[b] = r;

        // Reset counters for next graph replay: last finisher does it.
        __syncthreads();
        if (tid == 0) {
            const unsigned d = atomicAdd(&g_done, 1u);
            if (d == FIN_BLOCKS - 1) {
                atomicExch(&g_ctr,  0u);
                atomicExch(&g_done, 0u);
            }
        }
    }
}

extern "C" void kernel_launch(void* const* d_in, const int* in_sizes, int n_in,
                              void* d_out, int out_size) {
    const float* phi  = (const float*)d_in[0];   // (32768, 2, 10)
    const float* succ = (const float*)d_in[1];   // (128, 30, 30, 6)
    const float* w    = (const float*)d_in[2];   // (6,)
    float* out = (float*)d_out;                  // (32768, 2, 1)

    // Force 1 CTA per SM so wave 2 cannot start until wave 1 CTAs exit.
    static int attr_set = 0;
    if (!attr_set) {
        cudaFuncSetAttribute(fused_kernel,
                             cudaFuncAttributeMaxDynamicSharedMemorySize,
                             SMEM_FORCE);
        attr_set = 1;
    }
    fused_kernel<<<GRID, THREADS, SMEM_FORCE>>>(phi, succ, w, out);
}

// round 10
// speedup vs baseline: 1.7353x; 1.4706x over previous
#include <cuda_runtime.h>
#include <cooperative_groups.h>
#include <math.h>

namespace cg = cooperative_groups;

#define B_TOTAL 32768
#define X_DIM   30
#define Y_DIM   30
#define F_DIM   6
#define CELLS   (X_DIM * Y_DIM)      // 900
#define THREADS 256
#define PROD_BLOCKS 113               // 113 * 8 cells = 904 >= 900
#define GRID    148                   // one CTA per SM, single co-resident wave

__device__ float g_S[CELLS];

__global__ void __launch_bounds__(THREADS)
fused_coop_kernel(const float* __restrict__ phi,
                  const float* __restrict__ succ,
                  const float* __restrict__ w,
                  float* __restrict__ out) {
    const int tid = threadIdx.x;
    const int bid = blockIdx.x;

    const float w0 = __ldg(&w[0]), w1 = __ldg(&w[1]), w2 = __ldg(&w[2]);
    const float w3 = __ldg(&w[3]), w4 = __ldg(&w[4]), w5 = __ldg(&w[5]);

    // ---------- Consumer preload: issue phi DRAM loads first ----------
    const int idx = bid * THREADS + tid;          // 0 .. 37887
    const bool is_cons = idx < B_TOTAL;

    float pr0 = 0.f, pr1 = 0.f;
    int is0 = 0, ie0 = 0, is1 = 0, ie1 = 0;
    if (is_cons) {
        const float4* ph = (const float4*)(phi + (size_t)idx * 20);
        const float4 a0 = ph[0];
        const float4 a1 = ph[1];
        const float4 a2 = ph[2];
        const float4 a3 = ph[3];
        const float4 a4 = ph[4];

        pr0 = a0.x*w0 + a0.y*w1 + a0.z*w2 + a0.w*w3 + a1.x*w4 + a1.y*w5;
        pr1 = a2.z*w0 + a2.w*w1 + a3.x*w2 + a3.y*w3 + a3.z*w4 + a3.w*w5;

        is0 = (int)a1.z * Y_DIM + (int)a1.w;
        ie0 = (int)a2.x * Y_DIM + (int)a2.y;
        is1 = (int)a4.x * Y_DIM + (int)a4.y;
        ie1 = (int)a4.z * Y_DIM + (int)a4.w;
    }

    // ---------- Producer phase: blocks 0..112, 8 cells each ----------
    if (bid < PROD_BLOCKS) {
        const int h    = tid >> 7;
        const int p    = tid & 127;
        const int lane = tid & 31;
        const int w4g  = (tid >> 5) & 3;
        const int cell0 = bid * 8 + h * 4;
        const bool valid = cell0 < CELLS;

        __shared__ float smax[2][4][4];
        __shared__ float ssum[2][4][4][2];

        float v[4], x[4];
        if (valid) {
            // byte offset = p*21600 + cell0*24 (cell0 % 4 == 0) -> 16B aligned
            const float4* base =
                (const float4*)(succ + (size_t)p * (CELLS * F_DIM) + (size_t)cell0 * F_DIM);
            const float4 q0 = base[0], q1 = base[1], q2 = base[2];
            const float4 q3 = base[3], q4 = base[4], q5 = base[5];

            v[0] = q0.x*w0 + q0.y*w1 + q0.z*w2 + q0.w*w3 + q1.x*w4 + q1.y*w5;
            v[1] = q1.z*w0 + q1.w*w1 + q2.x*w2 + q2.y*w3 + q2.z*w4 + q2.w*w5;
            v[2] = q3.x*w0 + q3.y*w1 + q3.z*w2 + q3.w*w3 + q4.x*w4 + q4.y*w5;
            v[3] = q4.z*w0 + q4.w*w1 + q5.x*w2 + q5.y*w3 + q5.z*w4 + q5.w*w5;

#pragma unroll
            for (int j = 0; j < 4; ++j) x[j] = v[j] / 0.001f;   // match vs / T

#pragma unroll
            for (int j = 0; j < 4; ++j) {
                float mm = x[j];
#pragma unroll
                for (int s = 16; s > 0; s >>= 1)
                    mm = fmaxf(mm, __shfl_xor_sync(0xFFFFFFFFu, mm, s));
                if (lane == 0) smax[h][j][w4g] = mm;
            }
        }
        __syncthreads();

        if (valid) {
#pragma unroll
            for (int j = 0; j < 4; ++j) {
                const float mx = fmaxf(fmaxf(smax[h][j][0], smax[h][j][1]),
                                       fmaxf(smax[h][j][2], smax[h][j][3]));
                float e  = __expf(x[j] - mx);
                float ev = e * v[j];
#pragma unroll
                for (int s = 16; s > 0; s >>= 1) {
                    e  += __shfl_xor_sync(0xFFFFFFFFu, e,  s);
                    ev += __shfl_xor_sync(0xFFFFFFFFu, ev, s);
                }
                if (lane == 0) { ssum[h][j][w4g][0] = e; ssum[h][j][w4g][1] = ev; }
            }
        }
        __syncthreads();

        if (valid && (tid & 127) < 4) {
            const int j = tid & 3;
            const float se  = ssum[h][j][0][0] + ssum[h][j][1][0]
                            + ssum[h][j][2][0] + ssum[h][j][3][0];
            const float sev = ssum[h][j][0][1] + ssum[h][j][1][1]
                            + ssum[h][j][2][1] + ssum[h][j][3][1];
            g_S[cell0 + j] = sev / se;
        }
    }

    // ---------- Device-wide barrier (HW/driver-managed, orders memory) ----------
    cg::this_grid().sync();

    // ---------- Consumer finish ----------
    if (is_cons) {
        const float d0 = pr0 + (g_S[ie0] - g_S[is0]);
        const float d1 = pr1 + (g_S[ie1] - g_S[is1]);

        const float diff = d0 - d1;
        float2 r;
        r.x = 1.0f / (1.0f + __expf(-diff));
        r.y = 1.0f / (1.0f + __expf( diff));
        ((float2*)out)[idx] = r;
    }
}

extern "C" void kernel_launch(void* const* d_in, const int* in_sizes, int n_in,
                              void* d_out, int out_size) {
    const float* phi  = (const float*)d_in[0];   // (32768, 2, 10)
    const float* succ = (const float*)d_in[1];   // (128, 30, 30, 6)
    const float* w    = (const float*)d_in[2];   // (6,)
    float* out = (float*)d_out;                  // (32768, 2, 1)

    cudaLaunchConfig_t cfg = {};
    cfg.gridDim  = dim3(GRID);
    cfg.blockDim = dim3(THREADS);
    cfg.dynamicSmemBytes = 0;
    cfg.stream = 0;

    cudaLaunchAttribute attrs[1];
    attrs[0].id = cudaLaunchAttributeCooperative;
    attrs[0].val.cooperative = 1;
    cfg.attrs = attrs;
    cfg.numAttrs = 1;

    cudaLaunchKernelEx(&cfg, fused_coop_kernel, phi, succ, w, out);
}